// round 15
// baseline (speedup 1.0000x reference)
#include <cuda_runtime.h>
#include <math.h>

// Problem constants (fixed by setup_inputs)
#define NN      50000
#define HH      64
#define FIN     128
#define FE      16
#define EE      800000
#define ETOT    (EE + NN)
#define NEG_SLOPE 0.2f

// ---------------- scratch (device globals; no allocation allowed) ----------
__device__ float g_h    [NN * HH];   // h = x @ W
__device__ float g_agg  [NN * HH];   // segment-sum accumulator
__device__ float g_xbuf [NN * HH];   // layer output (next layer input)
__device__ float g_alpha[ETOT];      // per-edge alpha, then exp
__device__ float g_asrc [NN];
__device__ float g_adst [NN];
__device__ float g_amax [NN];
__device__ float g_denom[NN];
__device__ float g_w16  [16];        // We @ ae
__device__ float g_loopc;            // ea_mean . w16
__device__ float g_easum[16];        // column sums of edge_attr
__device__ float g_gsum [64];        // graph embedding accumulator

// ---------------- helpers ---------------------------------------------------
__device__ __forceinline__ void atomicMaxF(float* addr, float v) {
    if (v >= 0.0f) atomicMax(reinterpret_cast<int*>(addr), __float_as_int(v));
    else           atomicMin(reinterpret_cast<unsigned int*>(addr), __float_as_uint(v));
}

// ---------------- per-launch init ------------------------------------------
__global__ void k_zero_small() {
    int t = threadIdx.x;
    if (t < 16) g_easum[t] = 0.0f;
    if (t < 64) g_gsum[t]  = 0.0f;
}

// column-sum of edge_attr [E,16]
__global__ void k_ea_reduce(const float* __restrict__ ea, int E) {
    int col = threadIdx.x & 15;
    int row = threadIdx.x >> 4;           // 0..15
    float s = 0.0f;
    for (long long e = (long long)blockIdx.x * 16 + row; e < E;
         e += (long long)gridDim.x * 16)
        s += ea[e * 16 + col];
    __shared__ float sh[256];
    sh[threadIdx.x] = s;
    __syncthreads();
    if (threadIdx.x < 16) {
        float t = 0.0f;
        #pragma unroll
        for (int r = 0; r < 16; r++) t += sh[r * 16 + threadIdx.x];
        atomicAdd(&g_easum[threadIdx.x], t);
    }
}

// w16 = We @ ae ; loopc = ea_mean . w16
__global__ void k_w16(const float* __restrict__ We, const float* __restrict__ ae,
                      float Einv) {
    int c = threadIdx.x;
    if (c < 16) {
        float s = 0.0f;
        #pragma unroll
        for (int j = 0; j < 64; j++) s += We[c * 64 + j] * ae[j];
        g_w16[c] = s;
    }
    __syncthreads();
    if (c == 0) {
        float lc = 0.0f;
        #pragma unroll
        for (int i = 0; i < 16; i++) lc += g_easum[i] * Einv * g_w16[i];
        g_loopc = lc;
    }
}

// zero agg, init amax/denom
__global__ void k_init_layer(int n) {
    long long idx = (long long)blockIdx.x * blockDim.x + threadIdx.x;
    long long tot = (long long)n * HH;
    if (idx < tot) g_agg[idx] = 0.0f;
    if (idx < n) { g_amax[idx] = -INFINITY; g_denom[idx] = 0.0f; }
}

// h = x @ W ; asrc = h . a_s ; adst = h . a_d
// block: 64 (cols) x 4 (nodes)
__global__ void k_gemm(const float* __restrict__ x_in,
                       const float* __restrict__ W,
                       const float* __restrict__ a_s,
                       const float* __restrict__ a_d,
                       int n, int K, int use_xbuf) {
    __shared__ float xs[4][FIN];
    __shared__ float rs[4][64];
    __shared__ float rd[4][64];
    const float* xp = use_xbuf ? g_xbuf : x_in;

    int tx = threadIdx.x;          // 0..63  (H column)
    int ty = threadIdx.y;          // 0..3   (node in block)
    int node = blockIdx.x * 4 + ty;
    bool valid = node < n;

    if (valid) {
        xs[ty][tx] = xp[(size_t)node * K + tx];
        if (K == 128) xs[ty][tx + 64] = xp[(size_t)node * K + tx + 64];
    } else {
        xs[ty][tx] = 0.0f;
        if (K == 128) xs[ty][tx + 64] = 0.0f;
    }
    __syncthreads();

    float acc = 0.0f;
    #pragma unroll 8
    for (int k = 0; k < K; k++)
        acc = fmaf(xs[ty][k], W[k * 64 + tx], acc);

    if (valid) g_h[(size_t)node * 64 + tx] = acc;

    rs[ty][tx] = acc * a_s[tx];
    rd[ty][tx] = acc * a_d[tx];
    __syncthreads();
    #pragma unroll
    for (int off = 32; off > 0; off >>= 1) {
        if (tx < off) {
            rs[ty][tx] += rs[ty][tx + off];
            rd[ty][tx] += rd[ty][tx + off];
        }
        __syncthreads();
    }
    if (tx == 0 && valid) {
        g_asrc[node] = rs[ty][0];
        g_adst[node] = rd[ty][0];
    }
}

// pass A: alpha = leaky_relu(asrc[src]+adst[dst]+alpha_e); segment max
// edge_index is int32 [2,E] flat: src = ei[e], dst = ei[E+e]
__global__ void k_edgeA(const int* __restrict__ ei,
                        const float* __restrict__ ea, int E, int n) {
    int tot = E + n;
    for (long long e = (long long)blockIdx.x * blockDim.x + threadIdx.x;
         e < tot; e += (long long)gridDim.x * blockDim.x) {
        int s, d;
        float aev;
        if (e < E) {
            s = ei[e];
            d = ei[(long long)E + e];
            const float4* p = reinterpret_cast<const float4*>(ea + e * 16);
            float4 v0 = p[0], v1 = p[1], v2 = p[2], v3 = p[3];
            aev =  v0.x * g_w16[0]  + v0.y * g_w16[1]  + v0.z * g_w16[2]  + v0.w * g_w16[3]
                 + v1.x * g_w16[4]  + v1.y * g_w16[5]  + v1.z * g_w16[6]  + v1.w * g_w16[7]
                 + v2.x * g_w16[8]  + v2.y * g_w16[9]  + v2.z * g_w16[10] + v2.w * g_w16[11]
                 + v3.x * g_w16[12] + v3.y * g_w16[13] + v3.z * g_w16[14] + v3.w * g_w16[15];
        } else {
            s = d = (int)(e - E);
            aev = g_loopc;
        }
        if ((unsigned)s >= (unsigned)n || (unsigned)d >= (unsigned)n) continue;
        float a = g_asrc[s] + g_adst[d] + aev;
        a = a > 0.0f ? a : NEG_SLOPE * a;
        g_alpha[e] = a;
        atomicMaxF(&g_amax[d], a);
    }
}

// pass B: ex = exp(alpha - amax[dst]); segment sum
__global__ void k_edgeB(const int* __restrict__ ei, int E, int n) {
    int tot = E + n;
    for (long long e = (long long)blockIdx.x * blockDim.x + threadIdx.x;
         e < tot; e += (long long)gridDim.x * blockDim.x) {
        int d = (e < E) ? ei[(long long)E + e] : (int)(e - E);
        if ((unsigned)d >= (unsigned)n) continue;
        float ex = __expf(g_alpha[e] - g_amax[d]);
        g_alpha[e] = ex;
        atomicAdd(&g_denom[d], ex);
    }
}

// pass C: agg[dst] += h[src] * coef.
// One warp per edge; each lane handles 2 consecutive floats (float2 gather,
// 2 scalar atomicAdds -> coalesced REDG.32; 128-bit vector float atomics
// trap with err 717 on this target).
__global__ void k_edgeC(const int* __restrict__ ei, int E, int n) {
    int tot  = E + n;
    int lane = threadIdx.x & 31;
    long long gw = ((long long)blockIdx.x * blockDim.x + threadIdx.x) >> 5;
    long long nwarps = ((long long)gridDim.x * blockDim.x) >> 5;

    for (long long e = gw; e < tot; e += nwarps) {
        int s, d;
        if (e < E) { s = ei[e]; d = ei[(long long)E + e]; }
        else       { s = d = (int)(e - E); }
        if ((unsigned)s >= (unsigned)n || (unsigned)d >= (unsigned)n) continue;
        float coef = g_alpha[e] / (g_denom[d] + 1e-16f);
        float2 hv = reinterpret_cast<const float2*>(g_h + (size_t)s * 64)[lane];
        float* dst = g_agg + (size_t)d * 64 + (size_t)lane * 2;
        atomicAdd(dst + 0, hv.x * coef);
        atomicAdd(dst + 1, hv.y * coef);
    }
}

// finalize: x_next = elu(agg + b); accumulate into d_out node region
__global__ void k_finalize(const float* __restrict__ b, float* __restrict__ dout,
                           int n, int first) {
    long long tot = (long long)n * HH;
    for (long long idx = (long long)blockIdx.x * blockDim.x + threadIdx.x;
         idx < tot; idx += (long long)gridDim.x * blockDim.x) {
        int j = (int)(idx & 63);
        float v = g_agg[idx] + b[j];
        v = v > 0.0f ? v : expm1f(v);
        g_xbuf[idx] = v;
        if (first) dout[idx] = v;
        else       dout[idx] += v;
    }
}

// graph embedding partial sums
__global__ void k_gsum(const float* __restrict__ dout, int n) {
    int col = threadIdx.x & 63;
    int r   = threadIdx.x >> 6;          // 0..3
    float s = 0.0f;
    for (long long node = (long long)blockIdx.x * 4 + r; node < n;
         node += (long long)gridDim.x * 4)
        s += dout[node * 64 + col];
    __shared__ float sh[256];
    sh[threadIdx.x] = s;
    __syncthreads();
    if (threadIdx.x < 64) {
        float t = sh[threadIdx.x] + sh[64 + threadIdx.x] +
                  sh[128 + threadIdx.x] + sh[192 + threadIdx.x];
        atomicAdd(&g_gsum[threadIdx.x], t);
    }
}

__global__ void k_gwrite(float* __restrict__ dout, int n) {
    int t = threadIdx.x;
    if (t < 64) dout[(size_t)n * 64 + t] = g_gsum[t] / (float)n;
}

// ---------------------------------------------------------------------------
extern "C" void kernel_launch(void* const* d_in, const int* in_sizes, int n_in,
                              void* d_out, int out_size) {
    const float* x  = (const float*)d_in[0];
    const int*   ei = (const int*)d_in[1];       // int32 [2,E] flat
    const float* ea = (const float*)d_in[2];

    const float* W [3] = { (const float*)d_in[3],  (const float*)d_in[9],  (const float*)d_in[15] };
    const float* AS[3] = { (const float*)d_in[4],  (const float*)d_in[10], (const float*)d_in[16] };
    const float* AD[3] = { (const float*)d_in[5],  (const float*)d_in[11], (const float*)d_in[17] };
    const float* WE[3] = { (const float*)d_in[6],  (const float*)d_in[12], (const float*)d_in[18] };
    const float* AE[3] = { (const float*)d_in[7],  (const float*)d_in[13], (const float*)d_in[19] };
    const float* B [3] = { (const float*)d_in[8],  (const float*)d_in[14], (const float*)d_in[20] };

    const int E   = in_sizes[1] / 2;          // edge_index is [2,E]
    const int fin = in_sizes[3] / HH;          // W1 is [F_IN, H]
    const int n   = in_sizes[0] / fin;
    const int tot = E + n;

    float* out = (float*)d_out;

    k_zero_small<<<1, 64>>>();
    k_ea_reduce<<<512, 256>>>(ea, E);

    const int nb_nh   = (n * HH + 255) / 256;             // 12500
    const int nb_edge = (tot + 255) / 256;                // 3321
    const int nb_edC  = 2048;                             // grid-stride, warp/edge

    for (int l = 0; l < 3; l++) {
        int K = (l == 0) ? fin : HH;
        k_w16<<<1, 32>>>(WE[l], AE[l], 1.0f / (float)E);
        k_init_layer<<<nb_nh, 256>>>(n);
        k_gemm<<<(n + 3) / 4, dim3(64, 4)>>>(x, W[l], AS[l], AD[l], n, K, l > 0);
        k_edgeA<<<nb_edge, 256>>>(ei, ea, E, n);
        k_edgeB<<<nb_edge, 256>>>(ei, E, n);
        k_edgeC<<<nb_edC, 256>>>(ei, E, n);
        k_finalize<<<nb_nh, 256>>>(B[l], out, n, l == 0);
    }

    k_gsum<<<512, 256>>>(out, n);
    k_gwrite<<<1, 64>>>(out, n);
}

// round 16
// speedup vs baseline: 2.0215x; 2.0215x over previous
#include <cuda_runtime.h>
#include <math.h>

// Problem constants (fixed by setup_inputs)
#define NN      50000
#define HH      64
#define FIN     128
#define EE      800000
#define ETOT    (EE + NN)
#define NEG_SLOPE 0.2f

// ---------------- scratch (device globals; no allocation allowed) ----------
__device__ float g_h    [NN * HH];        // h = x @ W
__device__ float g_xbuf [NN * HH];        // layer output (next layer input)
__device__ float g_asrc [NN];
__device__ float g_adst [NN];
__device__ float g_w16all[48];            // w16 for 3 layers
__device__ float g_loopc3[3];             // self-loop edge logits, per layer
__device__ float g_easum[16];
__device__ float g_gsum [64];
__device__ int   g_cnt   [NN];            // histogram, then fill cursor
__device__ int   g_indptr[NN + 1];        // CSR row pointers (by dst)
__device__ int   g_bsum  [1024];          // scan block sums
__device__ int   g_src_sorted[ETOT];      // src node per dst-sorted edge
__device__ float g_aev_sorted[3 * ETOT];  // per-layer edge logit, dst-sorted
__device__ float g_ax   [ETOT];           // per-edge alpha / exp scratch

// ---------------- small init ------------------------------------------------
__global__ void k_zero_small() {
    int t = threadIdx.x;
    if (t < 16) g_easum[t] = 0.0f;
    if (t < 64) g_gsum[t]  = 0.0f;
}

__global__ void k_zero_cnt(int n) {
    for (int i = blockIdx.x * blockDim.x + threadIdx.x; i < n;
         i += gridDim.x * blockDim.x)
        g_cnt[i] = 0;
}

// column-sum of edge_attr [E,16]
__global__ void k_ea_reduce(const float* __restrict__ ea, int E) {
    int col = threadIdx.x & 15;
    int row = threadIdx.x >> 4;
    float s = 0.0f;
    for (long long e = (long long)blockIdx.x * 16 + row; e < E;
         e += (long long)gridDim.x * 16)
        s += ea[e * 16 + col];
    __shared__ float sh[256];
    sh[threadIdx.x] = s;
    __syncthreads();
    if (threadIdx.x < 16) {
        float t = 0.0f;
        #pragma unroll
        for (int r = 0; r < 16; r++) t += sh[r * 16 + threadIdx.x];
        atomicAdd(&g_easum[threadIdx.x], t);
    }
}

// w16[l] = We_l @ ae_l (all 3 layers); loopc_l = ea_mean . w16[l]
__global__ void k_w16all(const float* __restrict__ We0, const float* __restrict__ ae0,
                         const float* __restrict__ We1, const float* __restrict__ ae1,
                         const float* __restrict__ We2, const float* __restrict__ ae2,
                         float Einv) {
    int t = threadIdx.x;
    if (t < 48) {
        int l = t >> 4, c = t & 15;
        const float* We = (l == 0) ? We0 : (l == 1) ? We1 : We2;
        const float* ae = (l == 0) ? ae0 : (l == 1) ? ae1 : ae2;
        float s = 0.0f;
        #pragma unroll
        for (int j = 0; j < 64; j++) s += We[c * 64 + j] * ae[j];
        g_w16all[t] = s;
    }
    __syncthreads();
    if (t < 3) {
        float lc = 0.0f;
        #pragma unroll
        for (int i = 0; i < 16; i++) lc += g_easum[i] * Einv * g_w16all[t * 16 + i];
        g_loopc3[t] = lc;
    }
}

// ---------------- CSR build (by dst) ---------------------------------------
__global__ void k_hist(const int* __restrict__ ei, int E, int n) {
    int tot = E + n;
    for (int e = blockIdx.x * blockDim.x + threadIdx.x; e < tot;
         e += gridDim.x * blockDim.x) {
        int s, d;
        if (e < E) { s = ei[e]; d = ei[E + e]; }
        else       { s = d = e - E; }
        if ((unsigned)s >= (unsigned)n || (unsigned)d >= (unsigned)n) continue;
        atomicAdd(&g_cnt[d], 1);
    }
}

// inclusive scan within 256-chunk -> indptr[i+1]; block total -> bsum
__global__ void k_scan1(int n) {
    __shared__ int sh[256];
    int t = threadIdx.x;
    int i = blockIdx.x * 256 + t;
    sh[t] = (i < n) ? g_cnt[i] : 0;
    __syncthreads();
    #pragma unroll
    for (int off = 1; off < 256; off <<= 1) {
        int u = (t >= off) ? sh[t - off] : 0;
        __syncthreads();
        sh[t] += u;
        __syncthreads();
    }
    if (i < n) g_indptr[i + 1] = sh[t];
    if (t == 255) g_bsum[blockIdx.x] = sh[255];
}

// exclusive scan of block sums (nb <= 1024)
__global__ void k_scan2(int nb) {
    __shared__ int sh[1024];
    int t = threadIdx.x;
    sh[t] = (t < nb) ? g_bsum[t] : 0;
    __syncthreads();
    #pragma unroll
    for (int off = 1; off < 1024; off <<= 1) {
        int u = (t >= off) ? sh[t - off] : 0;
        __syncthreads();
        sh[t] += u;
        __syncthreads();
    }
    if (t < nb) g_bsum[t] = (t == 0) ? 0 : sh[t - 1];
}

__global__ void k_scan3(int n) {
    int i = blockIdx.x * 256 + threadIdx.x;
    if (i < n) g_indptr[i + 1] += g_bsum[blockIdx.x];
    if (i == 0) g_indptr[0] = 0;
}

// fill: compute 3-layer edge logits (single coalesced pass over ea) and
// scatter (src, aev0..2) into dst-sorted order.
__global__ void k_fill(const int* __restrict__ ei, const float* __restrict__ ea,
                       int E, int n) {
    __shared__ float w[48];
    __shared__ float lc[3];
    int t = threadIdx.x;
    if (t < 48) w[t] = g_w16all[t];
    if (t < 3)  lc[t] = g_loopc3[t];
    __syncthreads();

    int tot = E + n;
    for (int e = blockIdx.x * blockDim.x + t; e < tot;
         e += gridDim.x * blockDim.x) {
        int s, d;
        float a0, a1, a2;
        if (e < E) {
            s = ei[e]; d = ei[E + e];
            if ((unsigned)s >= (unsigned)n || (unsigned)d >= (unsigned)n) continue;
            const float4* p = reinterpret_cast<const float4*>(ea + (size_t)e * 16);
            float4 v0 = p[0], v1 = p[1], v2 = p[2], v3 = p[3];
            float f[16] = { v0.x, v0.y, v0.z, v0.w, v1.x, v1.y, v1.z, v1.w,
                            v2.x, v2.y, v2.z, v2.w, v3.x, v3.y, v3.z, v3.w };
            a0 = 0.0f; a1 = 0.0f; a2 = 0.0f;
            #pragma unroll
            for (int i = 0; i < 16; i++) {
                a0 += f[i] * w[i];
                a1 += f[i] * w[16 + i];
                a2 += f[i] * w[32 + i];
            }
        } else {
            s = d = e - E;
            a0 = lc[0]; a1 = lc[1]; a2 = lc[2];
        }
        int p = g_indptr[d] + atomicAdd(&g_cnt[d], 1);
        g_src_sorted[p] = s;
        g_aev_sorted[p] = a0;
        g_aev_sorted[ETOT + p] = a1;
        g_aev_sorted[2 * ETOT + p] = a2;
    }
}

// ---------------- per-layer kernels ----------------------------------------
// h = x @ W ; asrc = h . a_s ; adst = h . a_d
__global__ void k_gemm(const float* __restrict__ x_in,
                       const float* __restrict__ W,
                       const float* __restrict__ a_s,
                       const float* __restrict__ a_d,
                       int n, int K, int use_xbuf) {
    __shared__ float xs[4][FIN];
    __shared__ float rs[4][64];
    __shared__ float rd[4][64];
    const float* xp = use_xbuf ? g_xbuf : x_in;

    int tx = threadIdx.x;          // 0..63  (H column)
    int ty = threadIdx.y;          // 0..3   (node in block)
    int node = blockIdx.x * 4 + ty;
    bool valid = node < n;

    if (valid) {
        xs[ty][tx] = xp[(size_t)node * K + tx];
        if (K == 128) xs[ty][tx + 64] = xp[(size_t)node * K + tx + 64];
    } else {
        xs[ty][tx] = 0.0f;
        if (K == 128) xs[ty][tx + 64] = 0.0f;
    }
    __syncthreads();

    float acc = 0.0f;
    #pragma unroll 8
    for (int k = 0; k < K; k++)
        acc = fmaf(xs[ty][k], W[k * 64 + tx], acc);

    if (valid) g_h[(size_t)node * 64 + tx] = acc;

    rs[ty][tx] = acc * a_s[tx];
    rd[ty][tx] = acc * a_d[tx];
    __syncthreads();
    #pragma unroll
    for (int off = 32; off > 0; off >>= 1) {
        if (tx < off) {
            rs[ty][tx] += rs[ty][tx + off];
            rd[ty][tx] += rd[ty][tx + off];
        }
        __syncthreads();
    }
    if (tx == 0 && valid) {
        g_asrc[node] = rs[ty][0];
        g_adst[node] = rd[ty][0];
    }
}

// fused softmax + aggregate + elu + output accumulate. One warp per dst node.
__global__ void k_fused(int l, const float* __restrict__ b,
                        float* __restrict__ dout, int n, int first) {
    int lane = threadIdx.x & 31;
    int d = blockIdx.x * (blockDim.x >> 5) + (threadIdx.x >> 5);
    if (d >= n) return;

    int start = g_indptr[d], end = g_indptr[d + 1];
    const float* __restrict__ aev = g_aev_sorted + (size_t)l * ETOT;
    float adstv = g_adst[d];

    // sweep 1: logits + leaky relu + warp max
    float amax = -INFINITY;
    for (int i = start + lane; i < end; i += 32) {
        float a = g_asrc[g_src_sorted[i]] + adstv + aev[i];
        a = a > 0.0f ? a : NEG_SLOPE * a;
        g_ax[i] = a;
        amax = fmaxf(amax, a);
    }
    #pragma unroll
    for (int o = 16; o; o >>= 1)
        amax = fmaxf(amax, __shfl_xor_sync(0xffffffffu, amax, o));
    __syncwarp();

    // sweep 2: exp + warp sum
    float dsum = 0.0f;
    for (int i = start + lane; i < end; i += 32) {
        float ex = __expf(g_ax[i] - amax);
        g_ax[i] = ex;
        dsum += ex;
    }
    #pragma unroll
    for (int o = 16; o; o >>= 1)
        dsum += __shfl_xor_sync(0xffffffffu, dsum, o);
    float inv = 1.0f / (dsum + 1e-16f);
    __syncwarp();

    // sweep 3: accumulate h[src]*coef into registers (2 floats/lane)
    float ax = 0.0f, ay = 0.0f;
    int j = start;
    for (; j + 1 < end; j += 2) {
        float c0 = g_ax[j] * inv;
        float c1 = g_ax[j + 1] * inv;
        int   s0 = g_src_sorted[j];
        int   s1 = g_src_sorted[j + 1];
        float2 h0 = reinterpret_cast<const float2*>(g_h + (size_t)s0 * 64)[lane];
        float2 h1 = reinterpret_cast<const float2*>(g_h + (size_t)s1 * 64)[lane];
        ax += h0.x * c0 + h1.x * c1;
        ay += h0.y * c0 + h1.y * c1;
    }
    if (j < end) {
        float c = g_ax[j] * inv;
        int   s = g_src_sorted[j];
        float2 hv = reinterpret_cast<const float2*>(g_h + (size_t)s * 64)[lane];
        ax += hv.x * c;
        ay += hv.y * c;
    }

    // finalize: elu(agg + b), write next-layer input, accumulate output
    float vx = ax + b[2 * lane];
    float vy = ay + b[2 * lane + 1];
    vx = vx > 0.0f ? vx : expm1f(vx);
    vy = vy > 0.0f ? vy : expm1f(vy);
    size_t o = (size_t)d * 64 + (size_t)lane * 2;
    g_xbuf[o]     = vx;
    g_xbuf[o + 1] = vy;
    if (first) { dout[o] = vx;  dout[o + 1] = vy; }
    else       { dout[o] += vx; dout[o + 1] += vy; }
}

// ---------------- epilogue --------------------------------------------------
__global__ void k_gsum(const float* __restrict__ dout, int n) {
    int col = threadIdx.x & 63;
    int r   = threadIdx.x >> 6;
    float s = 0.0f;
    for (long long node = (long long)blockIdx.x * 4 + r; node < n;
         node += (long long)gridDim.x * 4)
        s += dout[node * 64 + col];
    __shared__ float sh[256];
    sh[threadIdx.x] = s;
    __syncthreads();
    if (threadIdx.x < 64) {
        float t = sh[threadIdx.x] + sh[64 + threadIdx.x] +
                  sh[128 + threadIdx.x] + sh[192 + threadIdx.x];
        atomicAdd(&g_gsum[threadIdx.x], t);
    }
}

__global__ void k_gwrite(float* __restrict__ dout, int n) {
    int t = threadIdx.x;
    if (t < 64) dout[(size_t)n * 64 + t] = g_gsum[t] / (float)n;
}

// ---------------------------------------------------------------------------
extern "C" void kernel_launch(void* const* d_in, const int* in_sizes, int n_in,
                              void* d_out, int out_size) {
    const float* x  = (const float*)d_in[0];
    const int*   ei = (const int*)d_in[1];       // int32 [2,E] flat
    const float* ea = (const float*)d_in[2];

    const float* W [3] = { (const float*)d_in[3],  (const float*)d_in[9],  (const float*)d_in[15] };
    const float* AS[3] = { (const float*)d_in[4],  (const float*)d_in[10], (const float*)d_in[16] };
    const float* AD[3] = { (const float*)d_in[5],  (const float*)d_in[11], (const float*)d_in[17] };
    const float* WE[3] = { (const float*)d_in[6],  (const float*)d_in[12], (const float*)d_in[18] };
    const float* AE[3] = { (const float*)d_in[7],  (const float*)d_in[13], (const float*)d_in[19] };
    const float* B [3] = { (const float*)d_in[8],  (const float*)d_in[14], (const float*)d_in[20] };

    const int E   = in_sizes[1] / 2;
    const int fin = in_sizes[3] / HH;
    const int n   = in_sizes[0] / fin;
    const int tot = E + n;

    float* out = (float*)d_out;

    const int nbS    = (n + 255) / 256;     // 196 scan blocks
    const int nbEdge = (tot + 255) / 256;

    // ---- one-time setup: edge logits + CSR by dst ----
    k_zero_small<<<1, 64>>>();
    k_ea_reduce<<<512, 256>>>(ea, E);
    k_w16all<<<1, 64>>>(WE[0], AE[0], WE[1], AE[1], WE[2], AE[2], 1.0f / (float)E);
    k_zero_cnt<<<nbS, 256>>>(n);
    k_hist<<<nbEdge, 256>>>(ei, E, n);
    k_scan1<<<nbS, 256>>>(n);
    k_scan2<<<1, 1024>>>(nbS);
    k_scan3<<<nbS, 256>>>(n);
    k_zero_cnt<<<nbS, 256>>>(n);
    k_fill<<<nbEdge, 256>>>(ei, ea, E, n);

    // ---- 3 GAT layers ----
    for (int l = 0; l < 3; l++) {
        int K = (l == 0) ? fin : HH;
        k_gemm<<<(n + 3) / 4, dim3(64, 4)>>>(x, W[l], AS[l], AD[l], n, K, l > 0);
        k_fused<<<(n + 7) / 8, 256>>>(l, B[l], out, n, l == 0);
    }

    k_gsum<<<512, 256>>>(out, n);
    k_gwrite<<<1, 64>>>(out, n);
}

// round 17
// speedup vs baseline: 2.1578x; 1.0675x over previous
#include <cuda_runtime.h>
#include <math.h>

// Problem constants (fixed by setup_inputs)
#define NN      50000
#define HH      64
#define FIN     128
#define EE      800000
#define ETOT    (EE + NN)
#define NEG_SLOPE 0.2f

// ---------------- scratch (device globals; no allocation allowed) ----------
__device__ float g_h    [NN * HH];        // h = x @ W
__device__ float g_xbuf [NN * HH];        // layer output (next layer input)
__device__ float g_asrc [NN];
__device__ float g_adst [NN];
__device__ float g_w16all[48];            // w16 for 3 layers
__device__ float g_loopc3[3];             // self-loop edge logits, per layer
__device__ float g_easum[16];
__device__ float g_gsum [64];
__device__ int   g_cnt   [NN];            // histogram, then fill cursor
__device__ int   g_indptr[NN + 1];        // CSR row pointers (by dst)
__device__ int   g_bsum  [1024];          // scan block sums
__device__ int4  g_edge  [ETOT];          // (src, a0bits, a1bits, a2bits) dst-sorted
__device__ float g_ax    [ETOT];          // slow-path scratch (deg>32 rows only)

// ---------------- small init ------------------------------------------------
__global__ void k_zero_small() {
    int t = threadIdx.x;
    if (t < 16) g_easum[t] = 0.0f;
    if (t < 64) g_gsum[t]  = 0.0f;
}

__global__ void k_zero_cnt(int n) {
    for (int i = blockIdx.x * blockDim.x + threadIdx.x; i < n;
         i += gridDim.x * blockDim.x)
        g_cnt[i] = 0;
}

// column-sum of edge_attr [E,16]
__global__ void k_ea_reduce(const float* __restrict__ ea, int E) {
    int col = threadIdx.x & 15;
    int row = threadIdx.x >> 4;
    float s = 0.0f;
    for (long long e = (long long)blockIdx.x * 16 + row; e < E;
         e += (long long)gridDim.x * 16)
        s += ea[e * 16 + col];
    __shared__ float sh[256];
    sh[threadIdx.x] = s;
    __syncthreads();
    if (threadIdx.x < 16) {
        float t = 0.0f;
        #pragma unroll
        for (int r = 0; r < 16; r++) t += sh[r * 16 + threadIdx.x];
        atomicAdd(&g_easum[threadIdx.x], t);
    }
}

// w16[l] = We_l @ ae_l (all 3 layers); loopc_l = ea_mean . w16[l]
__global__ void k_w16all(const float* __restrict__ We0, const float* __restrict__ ae0,
                         const float* __restrict__ We1, const float* __restrict__ ae1,
                         const float* __restrict__ We2, const float* __restrict__ ae2,
                         float Einv) {
    int t = threadIdx.x;
    if (t < 48) {
        int l = t >> 4, c = t & 15;
        const float* We = (l == 0) ? We0 : (l == 1) ? We1 : We2;
        const float* ae = (l == 0) ? ae0 : (l == 1) ? ae1 : ae2;
        float s = 0.0f;
        #pragma unroll
        for (int j = 0; j < 64; j++) s += We[c * 64 + j] * ae[j];
        g_w16all[t] = s;
    }
    __syncthreads();
    if (t < 3) {
        float lc = 0.0f;
        #pragma unroll
        for (int i = 0; i < 16; i++) lc += g_easum[i] * Einv * g_w16all[t * 16 + i];
        g_loopc3[t] = lc;
    }
}

// ---------------- CSR build (by dst) ---------------------------------------
__global__ void k_hist(const int* __restrict__ ei, int E, int n) {
    int tot = E + n;
    for (int e = blockIdx.x * blockDim.x + threadIdx.x; e < tot;
         e += gridDim.x * blockDim.x) {
        int s, d;
        if (e < E) { s = ei[e]; d = ei[E + e]; }
        else       { s = d = e - E; }
        if ((unsigned)s >= (unsigned)n || (unsigned)d >= (unsigned)n) continue;
        atomicAdd(&g_cnt[d], 1);
    }
}

// inclusive scan within 256-chunk -> indptr[i+1]; block total -> bsum
__global__ void k_scan1(int n) {
    __shared__ int sh[256];
    int t = threadIdx.x;
    int i = blockIdx.x * 256 + t;
    sh[t] = (i < n) ? g_cnt[i] : 0;
    __syncthreads();
    #pragma unroll
    for (int off = 1; off < 256; off <<= 1) {
        int u = (t >= off) ? sh[t - off] : 0;
        __syncthreads();
        sh[t] += u;
        __syncthreads();
    }
    if (i < n) g_indptr[i + 1] = sh[t];
    if (t == 255) g_bsum[blockIdx.x] = sh[255];
}

// exclusive scan of block sums (nb <= 1024)
__global__ void k_scan2(int nb) {
    __shared__ int sh[1024];
    int t = threadIdx.x;
    sh[t] = (t < nb) ? g_bsum[t] : 0;
    __syncthreads();
    #pragma unroll
    for (int off = 1; off < 1024; off <<= 1) {
        int u = (t >= off) ? sh[t - off] : 0;
        __syncthreads();
        sh[t] += u;
        __syncthreads();
    }
    if (t < nb) g_bsum[t] = (t == 0) ? 0 : sh[t - 1];
}

__global__ void k_scan3(int n) {
    int i = blockIdx.x * 256 + threadIdx.x;
    if (i < n) g_indptr[i + 1] += g_bsum[blockIdx.x];
    if (i == 0) g_indptr[0] = 0;
}

// fill: compute 3-layer edge logits (one pass over ea) and scatter the
// interleaved edge record (src, a0, a1, a2) into dst-sorted order.
__global__ void k_fill(const int* __restrict__ ei, const float* __restrict__ ea,
                       int E, int n) {
    __shared__ float w[48];
    __shared__ float lc[3];
    int t = threadIdx.x;
    if (t < 48) w[t] = g_w16all[t];
    if (t < 3)  lc[t] = g_loopc3[t];
    __syncthreads();

    int tot = E + n;
    for (int e = blockIdx.x * blockDim.x + t; e < tot;
         e += gridDim.x * blockDim.x) {
        int s, d;
        float a0, a1, a2;
        if (e < E) {
            s = ei[e]; d = ei[E + e];
            if ((unsigned)s >= (unsigned)n || (unsigned)d >= (unsigned)n) continue;
            const float4* p = reinterpret_cast<const float4*>(ea + (size_t)e * 16);
            float4 v0 = p[0], v1 = p[1], v2 = p[2], v3 = p[3];
            float f[16] = { v0.x, v0.y, v0.z, v0.w, v1.x, v1.y, v1.z, v1.w,
                            v2.x, v2.y, v2.z, v2.w, v3.x, v3.y, v3.z, v3.w };
            a0 = 0.0f; a1 = 0.0f; a2 = 0.0f;
            #pragma unroll
            for (int i = 0; i < 16; i++) {
                a0 += f[i] * w[i];
                a1 += f[i] * w[16 + i];
                a2 += f[i] * w[32 + i];
            }
        } else {
            s = d = e - E;
            a0 = lc[0]; a1 = lc[1]; a2 = lc[2];
        }
        int p = g_indptr[d] + atomicAdd(&g_cnt[d], 1);
        g_edge[p] = make_int4(s, __float_as_int(a0),
                                 __float_as_int(a1), __float_as_int(a2));
    }
}

// ---------------- per-layer kernels ----------------------------------------
// h = x @ W ; asrc = h . a_s ; adst = h . a_d
__global__ void k_gemm(const float* __restrict__ x_in,
                       const float* __restrict__ W,
                       const float* __restrict__ a_s,
                       const float* __restrict__ a_d,
                       int n, int K, int use_xbuf) {
    __shared__ float xs[4][FIN];
    __shared__ float rs[4][64];
    __shared__ float rd[4][64];
    const float* xp = use_xbuf ? g_xbuf : x_in;

    int tx = threadIdx.x;          // 0..63  (H column)
    int ty = threadIdx.y;          // 0..3   (node in block)
    int node = blockIdx.x * 4 + ty;
    bool valid = node < n;

    if (valid) {
        xs[ty][tx] = xp[(size_t)node * K + tx];
        if (K == 128) xs[ty][tx + 64] = xp[(size_t)node * K + tx + 64];
    } else {
        xs[ty][tx] = 0.0f;
        if (K == 128) xs[ty][tx + 64] = 0.0f;
    }
    __syncthreads();

    float acc = 0.0f;
    #pragma unroll 8
    for (int k = 0; k < K; k++)
        acc = fmaf(xs[ty][k], W[k * 64 + tx], acc);

    if (valid) g_h[(size_t)node * 64 + tx] = acc;

    rs[ty][tx] = acc * a_s[tx];
    rd[ty][tx] = acc * a_d[tx];
    __syncthreads();
    #pragma unroll
    for (int off = 32; off > 0; off >>= 1) {
        if (tx < off) {
            rs[ty][tx] += rs[ty][tx + off];
            rd[ty][tx] += rd[ty][tx + off];
        }
        __syncthreads();
    }
    if (tx == 0 && valid) {
        g_asrc[node] = rs[ty][0];
        g_adst[node] = rd[ty][0];
    }
}

// fused softmax + aggregate + elu + output accumulate. One warp per dst node.
// Fast path (deg<=32, ~99.8% of nodes): single-pass register-resident softmax.
__global__ void k_fused(int l, const float* __restrict__ b,
                        float* __restrict__ dout, int n, int first) {
    __shared__ int   ss[8][32];
    __shared__ float sc[8][32];
    int lane = threadIdx.x & 31;
    int w    = threadIdx.x >> 5;
    int d = blockIdx.x * 8 + w;
    if (d >= n) return;

    int start = g_indptr[d], end = g_indptr[d + 1];
    int deg = end - start;
    float adstv = g_adst[d];
    float ax = 0.0f, ay = 0.0f;

    if (deg <= 32) {
        // ---- fast path: one edge per lane, softmax fully in registers ----
        int   s = 0;
        float a = -INFINITY;
        if (lane < deg) {
            int4 ev = g_edge[start + lane];
            s = ev.x;
            float aev = (l == 0) ? __int_as_float(ev.y)
                      : (l == 1) ? __int_as_float(ev.z)
                                 : __int_as_float(ev.w);
            a = g_asrc[s] + adstv + aev;
            a = a > 0.0f ? a : NEG_SLOPE * a;
        }
        float amax = a;
        #pragma unroll
        for (int o = 16; o; o >>= 1)
            amax = fmaxf(amax, __shfl_xor_sync(0xffffffffu, amax, o));
        float ex = (lane < deg) ? __expf(a - amax) : 0.0f;
        float dsum = ex;
        #pragma unroll
        for (int o = 16; o; o >>= 1)
            dsum += __shfl_xor_sync(0xffffffffu, dsum, o);
        float inv = 1.0f / (dsum + 1e-16f);

        ss[w][lane] = s;
        sc[w][lane] = ex * inv;
        __syncwarp();

        #pragma unroll 4
        for (int j = 0; j < deg; j++) {
            float c = sc[w][j];
            float2 hv = *reinterpret_cast<const float2*>(
                g_h + (size_t)ss[w][j] * 64 + (size_t)lane * 2);
            ax = fmaf(hv.x, c, ax);
            ay = fmaf(hv.y, c, ay);
        }
    } else {
        // ---- slow path (rare, deg>32): 3-sweep with global scratch ----
        float amax = -INFINITY;
        for (int i = start + lane; i < end; i += 32) {
            int4 ev = g_edge[i];
            float aev = (l == 0) ? __int_as_float(ev.y)
                      : (l == 1) ? __int_as_float(ev.z)
                                 : __int_as_float(ev.w);
            float a = g_asrc[ev.x] + adstv + aev;
            a = a > 0.0f ? a : NEG_SLOPE * a;
            g_ax[i] = a;
            amax = fmaxf(amax, a);
        }
        #pragma unroll
        for (int o = 16; o; o >>= 1)
            amax = fmaxf(amax, __shfl_xor_sync(0xffffffffu, amax, o));
        __syncwarp();
        float dsum = 0.0f;
        for (int i = start + lane; i < end; i += 32) {
            float ex = __expf(g_ax[i] - amax);
            g_ax[i] = ex;
            dsum += ex;
        }
        #pragma unroll
        for (int o = 16; o; o >>= 1)
            dsum += __shfl_xor_sync(0xffffffffu, dsum, o);
        float inv = 1.0f / (dsum + 1e-16f);
        __syncwarp();
        for (int j = start; j < end; j++) {
            float c = g_ax[j] * inv;
            int   s = g_edge[j].x;
            float2 hv = *reinterpret_cast<const float2*>(
                g_h + (size_t)s * 64 + (size_t)lane * 2);
            ax = fmaf(hv.x, c, ax);
            ay = fmaf(hv.y, c, ay);
        }
    }

    // finalize: elu(agg + b), write next-layer input, accumulate output
    float vx = ax + b[2 * lane];
    float vy = ay + b[2 * lane + 1];
    vx = vx > 0.0f ? vx : expm1f(vx);
    vy = vy > 0.0f ? vy : expm1f(vy);
    size_t o = (size_t)d * 64 + (size_t)lane * 2;
    g_xbuf[o]     = vx;
    g_xbuf[o + 1] = vy;
    if (first) { dout[o] = vx;  dout[o + 1] = vy; }
    else       { dout[o] += vx; dout[o + 1] += vy; }
}

// ---------------- epilogue --------------------------------------------------
__global__ void k_gsum(const float* __restrict__ dout, int n) {
    int col = threadIdx.x & 63;
    int r   = threadIdx.x >> 6;
    float s = 0.0f;
    for (long long node = (long long)blockIdx.x * 4 + r; node < n;
         node += (long long)gridDim.x * 4)
        s += dout[node * 64 + col];
    __shared__ float sh[256];
    sh[threadIdx.x] = s;
    __syncthreads();
    if (threadIdx.x < 64) {
        float t = sh[threadIdx.x] + sh[64 + threadIdx.x] +
                  sh[128 + threadIdx.x] + sh[192 + threadIdx.x];
        atomicAdd(&g_gsum[threadIdx.x], t);
    }
}

__global__ void k_gwrite(float* __restrict__ dout, int n) {
    int t = threadIdx.x;
    if (t < 64) dout[(size_t)n * 64 + t] = g_gsum[t] / (float)n;
}

// ---------------------------------------------------------------------------
extern "C" void kernel_launch(void* const* d_in, const int* in_sizes, int n_in,
                              void* d_out, int out_size) {
    const float* x  = (const float*)d_in[0];
    const int*   ei = (const int*)d_in[1];       // int32 [2,E] flat
    const float* ea = (const float*)d_in[2];

    const float* W [3] = { (const float*)d_in[3],  (const float*)d_in[9],  (const float*)d_in[15] };
    const float* AS[3] = { (const float*)d_in[4],  (const float*)d_in[10], (const float*)d_in[16] };
    const float* AD[3] = { (const float*)d_in[5],  (const float*)d_in[11], (const float*)d_in[17] };
    const float* WE[3] = { (const float*)d_in[6],  (const float*)d_in[12], (const float*)d_in[18] };
    const float* AE[3] = { (const float*)d_in[7],  (const float*)d_in[13], (const float*)d_in[19] };
    const float* B [3] = { (const float*)d_in[8],  (const float*)d_in[14], (const float*)d_in[20] };

    const int E   = in_sizes[1] / 2;
    const int fin = in_sizes[3] / HH;
    const int n   = in_sizes[0] / fin;
    const int tot = E + n;

    float* out = (float*)d_out;

    const int nbS    = (n + 255) / 256;
    const int nbEdge = (tot + 255) / 256;

    // ---- one-time setup: edge logits + CSR by dst ----
    k_zero_small<<<1, 64>>>();
    k_ea_reduce<<<512, 256>>>(ea, E);
    k_w16all<<<1, 64>>>(WE[0], AE[0], WE[1], AE[1], WE[2], AE[2], 1.0f / (float)E);
    k_zero_cnt<<<nbS, 256>>>(n);
    k_hist<<<nbEdge, 256>>>(ei, E, n);
    k_scan1<<<nbS, 256>>>(n);
    k_scan2<<<1, 1024>>>(nbS);
    k_scan3<<<nbS, 256>>>(n);
    k_zero_cnt<<<nbS, 256>>>(n);
    k_fill<<<nbEdge, 256>>>(ei, ea, E, n);

    // ---- 3 GAT layers ----
    for (int l = 0; l < 3; l++) {
        int K = (l == 0) ? fin : HH;
        k_gemm<<<(n + 3) / 4, dim3(64, 4)>>>(x, W[l], AS[l], AD[l], n, K, l > 0);
        k_fused<<<(n + 7) / 8, 256>>>(l, B[l], out, n, l == 0);
    }

    k_gsum<<<512, 256>>>(out, n);
    k_gwrite<<<1, 64>>>(out, n);
}